// round 8
// baseline (speedup 1.0000x reference)
#include <cuda_runtime.h>
#include <cuda_fp16.h>
#include <math.h>

#define NV_MAX   1048576
#define MAX_SEG  50000
#define D        12
#define ROW_PAD  16          // halves per padded row = 32 bytes = 1 L2 sector
#define EPS      1e-12f
#define CHUNK    4096        // seg-id staging tile (16KB smem)
#define VPB      512         // voxels per block
#define VPP      4           // voxels per lane-pair (flat-loop balanced)

__device__ int g_start[NV_MAX];
__device__ int g_end[NV_MAX];
__device__ __align__(32) __half g_tab[MAX_SEG * ROW_PAD];

// Fused prep: blocks [0, bblocks) find run boundaries (4 tokens/thread, with
// gap-fill so bounds are monotone); remaining blocks repack the table to fp16.
__global__ __launch_bounds__(256) void k_prep(const int*   __restrict__ vox,
                                              const float* __restrict__ table,
                                              int T, int n_voxels,
                                              int rows, int bblocks) {
    if (blockIdx.x < (unsigned)bblocks) {
        int i = blockIdx.x * 256 + threadIdx.x;
        int base = i * 4;
        if (base >= T) return;

        int4 q = __ldg((const int4*)vox + i);
        int vals[5];
        vals[0] = q.x; vals[1] = q.y; vals[2] = q.z; vals[3] = q.w;
        vals[4] = (base + 4 >= T) ? -1 : __ldg(vox + base + 4);

        if (base == 0) {
            for (int w = 0; w < vals[0]; w++) { g_start[w] = 0; g_end[w] = 0; }
            g_start[vals[0]] = 0;
        }
#pragma unroll
        for (int j = 0; j < 4; j++) {
            int idx = base + j;
            int cur = vals[j];
            if (idx == T - 1) {
                g_end[cur] = T;
                for (int w = cur + 1; w < n_voxels; w++) { g_start[w] = T; g_end[w] = T; }
            } else {
                int nx = vals[j + 1];
                if (nx != cur) {
                    g_end[cur]  = idx + 1;
                    g_start[nx] = idx + 1;
                    for (int w = cur + 1; w < nx; w++) { g_start[w] = idx + 1; g_end[w] = idx + 1; }
                }
            }
        }
    } else {
        int r = (blockIdx.x - bblocks) * 256 + threadIdx.x;
        if (r >= rows) return;
        const float4* src = (const float4*)(table + (size_t)r * D);
        float4 a = __ldg(src + 0);
        float4 b = __ldg(src + 1);
        float4 c = __ldg(src + 2);
        __half2 h[8];
        h[0] = __floats2half2_rn(a.x, a.y);
        h[1] = __floats2half2_rn(a.z, a.w);
        h[2] = __floats2half2_rn(b.x, b.y);
        h[3] = __floats2half2_rn(b.z, b.w);
        h[4] = __floats2half2_rn(c.x, c.y);
        h[5] = __floats2half2_rn(c.z, c.w);
        h[6] = __floats2half2_rn(0.f, 0.f);
        h[7] = __floats2half2_rn(0.f, 0.f);
        uint4* dst = (uint4*)(g_tab + (size_t)r * ROW_PAD);
        dst[0] = *(uint4*)&h[0];
        dst[1] = *(uint4*)&h[4];
    }
}

#define H2(u) (*(const __half2*)&(u))

// Pair-cooperative, load-balanced pool. Lanes (2k,2k+1) share VPP consecutive
// voxels as ONE flat token loop (sum of counts -> far lower warp-max skew).
// Even lane handles dims 0-7, odd lane dims 8-11(+pad). 1 wavefront/token.
__global__ __launch_bounds__(256) void k_pool(const int* __restrict__ seg,
                                              float*     __restrict__ out,
                                              int n_voxels) {
    __shared__ int s_seg[CHUNK];

    int tid   = threadIdx.x;
    int lane  = tid & 31;
    int p     = tid & 1;
    unsigned pairmask = 0x3u << (lane & ~1);

    int v0    = blockIdx.x * VPB;
    int vL    = min(v0 + VPB - 1, n_voxels - 1);
    int vbase = v0 + (tid >> 1) * VPP;
    int vlast = min(vbase + VPP - 1, n_voxels - 1);
    bool act  = (vbase < n_voxels);

    int rs = g_start[v0];
    int re = g_end[vL];

    int t   = act ? g_start[vbase] : re;   // next token to consume
    int e_p = act ? g_end[vlast]   : re;   // pair range end
    int cur   = vbase;
    int e_cur = act ? g_end[cur] : 0;
    int cnt   = 0;

    float acc[8];
#pragma unroll
    for (int d = 0; d < 8; d++) acc[d] = 0.0f;

    // flush current voxel: mean, pair-combined L2 norm, store, advance.
    auto flush = [&]() {
        float invc = 1.0f / (float)(cnt > 0 ? cnt : 1);
        float m[8];
        float n2 = 0.0f;
        int nd = p ? 4 : 8;
#pragma unroll
        for (int d = 0; d < 8; d++) {
            m[d] = acc[d] * invc;
            if (d < nd) n2 += m[d] * m[d];
        }
        n2 += __shfl_xor_sync(pairmask, n2, 1);
        float inv = 1.0f / fmaxf(sqrtf(n2), EPS);
        float4* orow = (float4*)(out + (size_t)cur * D);
        if (p == 0) {
            orow[0] = make_float4(m[0] * inv, m[1] * inv, m[2] * inv, m[3] * inv);
            orow[1] = make_float4(m[4] * inv, m[5] * inv, m[6] * inv, m[7] * inv);
        } else {
            orow[2] = make_float4(m[0] * inv, m[1] * inv, m[2] * inv, m[3] * inv);
        }
#pragma unroll
        for (int d = 0; d < 8; d++) acc[d] = 0.0f;
        cnt = 0;
        cur++;
        e_cur = (cur <= vlast) ? g_end[cur] : 0x7FFFFFFF;
    };

    auto accum = [&](uint4 q) {
        float2 f;
        f = __half22float2(H2(q.x)); acc[0] += f.x; acc[1] += f.y;
        f = __half22float2(H2(q.y)); acc[2] += f.x; acc[3] += f.y;
        f = __half22float2(H2(q.z)); acc[4] += f.x; acc[5] += f.y;
        f = __half22float2(H2(q.w)); acc[6] += f.x; acc[7] += f.y;
        cnt++;
    };

    for (int cbase = rs; cbase < re; cbase += CHUNK) {
        int clim = min(re, cbase + CHUNK);
        __syncthreads();
        for (int j = cbase + tid; j < clim; j += 256)
            s_seg[j - cbase] = __ldg(seg + j);
        __syncthreads();

        int tl = min(e_p, clim);
        // unrolled by 2: both gathers in flight before consumption
        while (t + 1 < tl) {
            int sg0 = s_seg[t - cbase];
            int sg1 = s_seg[t + 1 - cbase];
            uint4 q0 = __ldg((const uint4*)(g_tab + (size_t)sg0 * ROW_PAD) + p);
            uint4 q1 = __ldg((const uint4*)(g_tab + (size_t)sg1 * ROW_PAD) + p);
            while (t >= e_cur) flush();
            accum(q0);
            t++;
            while (t >= e_cur) flush();
            accum(q1);
            t++;
        }
        if (t < tl) {
            int sg = s_seg[t - cbase];
            uint4 q = __ldg((const uint4*)(g_tab + (size_t)sg * ROW_PAD) + p);
            while (t >= e_cur) flush();
            accum(q);
            t++;
        }
    }

    // trailing: last voxel's sums + any trailing empty voxels
    while (cur <= vlast && vbase < n_voxels) flush();
}

extern "C" void kernel_launch(void* const* d_in, const int* in_sizes, int n_in,
                              void* d_out, int out_size) {
    const float* table = (const float*)d_in[0];
    const int*   seg   = (const int*)  d_in[1];
    const int*   vox   = (const int*)  d_in[2];
    float*       out   = (float*)      d_out;

    int rows     = in_sizes[0] / D;
    int T        = in_sizes[1];
    int n_voxels = out_size / D;

    int bblocks = (T / 4 + 255) / 256;
    int rblocks = (rows + 255) / 256;
    k_prep<<<bblocks + rblocks, 256>>>(vox, table, T, n_voxels, rows, bblocks);
    k_pool<<<(n_voxels + VPB - 1) / VPB, 256>>>(seg, out, n_voxels);
}

// round 9
// speedup vs baseline: 1.3810x; 1.3810x over previous
#include <cuda_runtime.h>
#include <cuda_fp16.h>
#include <math.h>

#define NV_MAX   1048576
#define MAX_SEG  50000
#define D        12
#define ROW_PAD  16          // halves per padded row = 32 bytes = 1 L2 sector
#define EPS      1e-12f
#define CHUNK    2048        // seg-id staging tile (8KB smem)
#define VPB      256         // voxels per block (2 per lane-pair, dual-stream)

__device__ int g_start[NV_MAX];
__device__ int g_end[NV_MAX];
__device__ __align__(32) __half g_tab[MAX_SEG * ROW_PAD];

// Fused prep: blocks [0, bblocks) find run boundaries (4 tokens/thread, with
// gap-fill so bounds are monotone/contiguous); remaining blocks repack table.
__global__ __launch_bounds__(256) void k_prep(const int*   __restrict__ vox,
                                              const float* __restrict__ table,
                                              int T, int n_voxels,
                                              int rows, int bblocks) {
    if (blockIdx.x < (unsigned)bblocks) {
        int i = blockIdx.x * 256 + threadIdx.x;
        int base = i * 4;
        if (base >= T) return;

        int4 q = __ldg((const int4*)vox + i);
        int vals[5];
        vals[0] = q.x; vals[1] = q.y; vals[2] = q.z; vals[3] = q.w;
        vals[4] = (base + 4 >= T) ? -1 : __ldg(vox + base + 4);

        if (base == 0) {
            for (int w = 0; w < vals[0]; w++) { g_start[w] = 0; g_end[w] = 0; }
            g_start[vals[0]] = 0;
        }
#pragma unroll
        for (int j = 0; j < 4; j++) {
            int idx = base + j;
            int cur = vals[j];
            if (idx == T - 1) {
                g_end[cur] = T;
                for (int w = cur + 1; w < n_voxels; w++) { g_start[w] = T; g_end[w] = T; }
            } else {
                int nx = vals[j + 1];
                if (nx != cur) {
                    g_end[cur]  = idx + 1;
                    g_start[nx] = idx + 1;
                    for (int w = cur + 1; w < nx; w++) { g_start[w] = idx + 1; g_end[w] = idx + 1; }
                }
            }
        }
    } else {
        int r = (blockIdx.x - bblocks) * 256 + threadIdx.x;
        if (r >= rows) return;
        const float4* src = (const float4*)(table + (size_t)r * D);
        float4 a = __ldg(src + 0);
        float4 b = __ldg(src + 1);
        float4 c = __ldg(src + 2);
        __half2 h[8];
        h[0] = __floats2half2_rn(a.x, a.y);
        h[1] = __floats2half2_rn(a.z, a.w);
        h[2] = __floats2half2_rn(b.x, b.y);
        h[3] = __floats2half2_rn(b.z, b.w);
        h[4] = __floats2half2_rn(c.x, c.y);
        h[5] = __floats2half2_rn(c.z, c.w);
        h[6] = __floats2half2_rn(0.f, 0.f);
        h[7] = __floats2half2_rn(0.f, 0.f);
        uint4* dst = (uint4*)(g_tab + (size_t)r * ROW_PAD);
        dst[0] = *(uint4*)&h[0];
        dst[1] = *(uint4*)&h[4];
    }
}

#define H2(u) (*(const __half2*)&(u))

__device__ __forceinline__ void acc8(float* acc, uint4 q) {
    float2 f;
    f = __half22float2(H2(q.x)); acc[0] += f.x; acc[1] += f.y;
    f = __half22float2(H2(q.y)); acc[2] += f.x; acc[3] += f.y;
    f = __half22float2(H2(q.z)); acc[4] += f.x; acc[5] += f.y;
    f = __half22float2(H2(q.w)); acc[6] += f.x; acc[7] += f.y;
}

// Dual-stream pair-cooperative pool. Lanes (2k,2k+1) share voxels (2q, 2q+1);
// both token loops advance per iteration with predicated loads -> warp skew
// drops from max(Poisson(8)) to max(max(c1,c2)) with zero per-token branching.
// Even lane handles dims 0-7, odd lane dims 8-11(+pad). 1 wavefront/token.
__global__ __launch_bounds__(256) void k_pool(const int* __restrict__ seg,
                                              float*     __restrict__ out,
                                              int n_voxels) {
    __shared__ int s_seg[CHUNK];

    int tid  = threadIdx.x;
    int lane = tid & 31;
    int p    = tid & 1;
    unsigned pairmask = 0x3u << (lane & ~1);

    int v0 = blockIdx.x * VPB;
    int vL = min(v0 + VPB - 1, n_voxels - 1);
    int vA = v0 + (tid >> 1) * 2;
    int vB = vA + 1;

    int rs = g_start[v0];
    int re = g_end[vL];

    int tA, eA, tB, eB;
    if (vA < n_voxels) { tA = g_start[vA]; eA = g_end[vA]; }
    else               { tA = re;          eA = re;        }
    // bounds are contiguous (gap-fill): g_start[vB] == g_end[vA]
    if (vB < n_voxels) { tB = eA; eB = g_end[vB]; }
    else               { tB = re; eB = re;        }
    int sA = tA, sB = tB;

    float accA[8], accB[8];
#pragma unroll
    for (int d = 0; d < 8; d++) { accA[d] = 0.0f; accB[d] = 0.0f; }

    for (int cbase = rs; cbase < re; cbase += CHUNK) {
        int clim = min(re, cbase + CHUNK);
        __syncthreads();
        for (int j = cbase + tid; j < clim; j += 256)
            s_seg[j - cbase] = __ldg(seg + j);
        __syncthreads();

        int eAc = min(eA, clim);
        int eBc = min(eB, clim);

        while (tA < eAc || tB < eBc) {
            bool a = tA < eAc;
            bool b = tB < eBc;
            uint4 qA = make_uint4(0u, 0u, 0u, 0u);
            uint4 qB = make_uint4(0u, 0u, 0u, 0u);
            if (a) {
                int sg = s_seg[tA - cbase];
                qA = __ldg((const uint4*)(g_tab + (size_t)sg * ROW_PAD) + p);
            }
            if (b) {
                int sg = s_seg[tB - cbase];
                qB = __ldg((const uint4*)(g_tab + (size_t)sg * ROW_PAD) + p);
            }
            acc8(accA, qA);           // zeros harmless when inactive
            acc8(accB, qB);
            tA += a ? 1 : 0;
            tB += b ? 1 : 0;
        }
    }

    // Epilogue per stream: mean, pair-combined L2 norm, store.
    {
        int cnt = eA - sA;
        float invc = 1.0f / (float)(cnt > 0 ? cnt : 1);
        float m[8];
        float n2 = 0.0f;
        int nd = p ? 4 : 8;
#pragma unroll
        for (int d = 0; d < 8; d++) {
            m[d] = accA[d] * invc;
            if (d < nd) n2 += m[d] * m[d];
        }
        n2 += __shfl_xor_sync(pairmask, n2, 1);
        float inv = 1.0f / fmaxf(sqrtf(n2), EPS);
        if (vA < n_voxels) {
            float4* orow = (float4*)(out + (size_t)vA * D);
            if (p == 0) {
                orow[0] = make_float4(m[0] * inv, m[1] * inv, m[2] * inv, m[3] * inv);
                orow[1] = make_float4(m[4] * inv, m[5] * inv, m[6] * inv, m[7] * inv);
            } else {
                orow[2] = make_float4(m[0] * inv, m[1] * inv, m[2] * inv, m[3] * inv);
            }
        }
    }
    {
        int cnt = eB - sB;
        float invc = 1.0f / (float)(cnt > 0 ? cnt : 1);
        float m[8];
        float n2 = 0.0f;
        int nd = p ? 4 : 8;
#pragma unroll
        for (int d = 0; d < 8; d++) {
            m[d] = accB[d] * invc;
            if (d < nd) n2 += m[d] * m[d];
        }
        n2 += __shfl_xor_sync(pairmask, n2, 1);
        float inv = 1.0f / fmaxf(sqrtf(n2), EPS);
        if (vB < n_voxels) {
            float4* orow = (float4*)(out + (size_t)vB * D);
            if (p == 0) {
                orow[0] = make_float4(m[0] * inv, m[1] * inv, m[2] * inv, m[3] * inv);
                orow[1] = make_float4(m[4] * inv, m[5] * inv, m[6] * inv, m[7] * inv);
            } else {
                orow[2] = make_float4(m[0] * inv, m[1] * inv, m[2] * inv, m[3] * inv);
            }
        }
    }
}

extern "C" void kernel_launch(void* const* d_in, const int* in_sizes, int n_in,
                              void* d_out, int out_size) {
    const float* table = (const float*)d_in[0];
    const int*   seg   = (const int*)  d_in[1];
    const int*   vox   = (const int*)  d_in[2];
    float*       out   = (float*)      d_out;

    int rows     = in_sizes[0] / D;
    int T        = in_sizes[1];
    int n_voxels = out_size / D;

    int bblocks = (T / 4 + 255) / 256;
    int rblocks = (rows + 255) / 256;
    k_prep<<<bblocks + rblocks, 256>>>(vox, table, T, n_voxels, rows, bblocks);
    k_pool<<<(n_voxels + VPB - 1) / VPB, 256>>>(seg, out, n_voxels);
}